// round 1
// baseline (speedup 1.0000x reference)
#include <cuda_runtime.h>

// ---------------------------------------------------------------------------
// Sparse masked 3D U-Net (presetUResNet) on 96^3 grid, fp32.
// Strategy: compact occupied-voxel lists per level; gather-style convs write
// only occupied outputs into zeroed dense buffers (channel-major CDHW).
// ---------------------------------------------------------------------------

constexpr int D0 = 96, D1 = 48, D2 = 24;
constexpr int V0 = D0 * D0 * D0;   // 884736
constexpr int V1 = D1 * D1 * D1;   // 110592
constexpr int V2 = D2 * D2 * D2;   // 13824

// ---- scratch arena layout (floats) ----
constexpr int OFF_XM    = 0;                    // 1  * V0 (masked input)
constexpr int OFF_SKIP0 = OFF_XM    + V0;       // 16 * V0
constexpr int OFF_UP1   = OFF_SKIP0 + 16 * V0;  // 16 * V0
constexpr int OFF_T32   = OFF_UP1   + 16 * V0;  // 32 * V0
constexpr int OFF_HA    = OFF_T32   + 32 * V0;  // 32 * V1
constexpr int OFF_HB    = OFF_HA    + 32 * V1;  // 32 * V1
constexpr int OFF_S1    = OFF_HB    + 32 * V1;  // 32 * V1
constexpr int OFF_H64   = OFF_S1    + 32 * V1;  // 64 * V1
constexpr int OFF_CA    = OFF_H64   + 64 * V1;  // 64 * V2
constexpr int OFF_CB    = OFF_CA    + 64 * V2;  // 64 * V2
constexpr int FEAT_END  = OFF_CB    + 64 * V2;
constexpr int OFF_M1    = FEAT_END;             // V1 mask
constexpr int OFF_M2    = OFF_M1 + V1;          // V2 mask
constexpr int OFF_W     = OFF_M2 + V2;
// transposed weights: layout [ci*K3 + tap][Copad]
constexpr int WO_IN  = OFF_W;
constexpr int WO_E0D = WO_IN  + 1  * 27 * 16;
constexpr int WO_E0A = WO_E0D + 16 * 8  * 32;
constexpr int WO_E0B = WO_E0A + 32 * 27 * 32;
constexpr int WO_E1D = WO_E0B + 32 * 27 * 32;
constexpr int WO_E1A = WO_E1D + 32 * 8  * 64;
constexpr int WO_E1B = WO_E1A + 64 * 27 * 64;
constexpr int WO_D0U = WO_E1B + 64 * 27 * 64;
constexpr int WO_D0A = WO_D0U + 64 * 8  * 32;
constexpr int WO_D0B = WO_D0A + 64 * 27 * 64;
constexpr int WO_D1U = WO_D0B + 64 * 27 * 32;
constexpr int WO_D1A = WO_D1U + 32 * 8  * 16;
constexpr int WO_D1B = WO_D1A + 32 * 27 * 32;
constexpr int WO_OA  = WO_D1B + 32 * 27 * 16;
constexpr int WO_OB  = WO_OA  + 16 * 27 * 16;
constexpr int SCRATCH_TOTAL = WO_OB + 16 * 27 * 8;

__device__ __align__(256) float g_scratch[SCRATCH_TOTAL];
__device__ int g_list0[V0];
__device__ int g_list1[V1];
__device__ int g_list2[V2];
__device__ int g_cnt[4];

// ---------------------------------------------------------------------------
// utility kernels
// ---------------------------------------------------------------------------

__global__ void zero_all_kernel(float* __restrict__ out, int outn) {
    long stride = (long)gridDim.x * blockDim.x;
    long gt = (long)blockIdx.x * blockDim.x + threadIdx.x;
    float4 z4 = make_float4(0.f, 0.f, 0.f, 0.f);
    float4* s4 = reinterpret_cast<float4*>(g_scratch);
    for (long i = gt; i < FEAT_END / 4; i += stride) s4[i] = z4;
    float4* o4 = reinterpret_cast<float4*>(out);
    for (long i = gt; i < outn / 4; i += stride) o4[i] = z4;
    if (gt == 0) { g_cnt[0] = 0; g_cnt[1] = 0; g_cnt[2] = 0; g_cnt[3] = 0; }
}

__global__ void mask_mul_kernel(const float* __restrict__ x,
                                const float* __restrict__ m,
                                float* __restrict__ out, int n) {
    for (int i = blockIdx.x * blockDim.x + threadIdx.x; i < n;
         i += gridDim.x * blockDim.x)
        out[i] = x[i] * m[i];
}

__global__ void maxpool_mask_kernel(const float* __restrict__ fin,
                                    float* __restrict__ out, int Dc) {
    int Df = Dc * 2;
    int n = Dc * Dc * Dc;
    for (int i = blockIdx.x * blockDim.x + threadIdx.x; i < n;
         i += gridDim.x * blockDim.x) {
        int x = i % Dc, y = (i / Dc) % Dc, z = i / (Dc * Dc);
        float m = 0.f;
        #pragma unroll
        for (int dz = 0; dz < 2; dz++)
            #pragma unroll
            for (int dy = 0; dy < 2; dy++)
                #pragma unroll
                for (int dx = 0; dx < 2; dx++) {
                    int fi = ((2 * z + dz) * Df + (2 * y + dy)) * Df + (2 * x + dx);
                    m = fmaxf(m, fin[fi]);
                }
        out[i] = m;
    }
}

__global__ void build_list_kernel(const float* __restrict__ mask, int n,
                                  int* __restrict__ list, int* __restrict__ cnt) {
    int lane = threadIdx.x & 31;
    for (int i = blockIdx.x * blockDim.x + threadIdx.x; i < n + 31;
         i += gridDim.x * blockDim.x) {
        bool pred = (i < n) && (mask[i] > 0.5f);
        unsigned bal = __ballot_sync(0xffffffffu, pred);
        int leader = __ffs(bal) - 1;
        int base = 0;
        if (bal && lane == leader) base = atomicAdd(cnt, __popc(bal));
        base = __shfl_sync(0xffffffffu, base, leader < 0 ? 0 : leader);
        if (pred) list[base + __popc(bal & ((1u << lane) - 1))] = i;
    }
}

// weights: w[(o*Cin + ci)*K3 + t]  -->  wt[(ci*K3 + t)*Copad + o]  (pad zeros)
__global__ void transpose_w_kernel(const float* __restrict__ w,
                                   float* __restrict__ wt,
                                   int Cout, int Cin, int K3, int Copad) {
    int total = Cin * K3 * Copad;
    for (int i = blockIdx.x * blockDim.x + threadIdx.x; i < total;
         i += gridDim.x * blockDim.x) {
        int o = i % Copad;
        int r = i / Copad;
        int ci = r / K3, t = r % K3;
        wt[i] = (o < Cout) ? w[(o * Cin + ci) * K3 + t] : 0.f;
    }
}

// ---------------------------------------------------------------------------
// gather conv kernels (sparse outputs from compacted lists)
// ---------------------------------------------------------------------------

template <int CINA, int CINB, int COUT, int COPAD, bool RELU>
__global__ __launch_bounds__(256)
void conv3_kernel(const float* __restrict__ inA, const float* __restrict__ inB,
                  const float* __restrict__ wt, float* __restrict__ out,
                  const int* __restrict__ list, const int* __restrict__ cnt,
                  int cntIdx, int D) {
    const int vol = D * D * D;
    const int CG = COPAD / 4;
    int n = cnt[cntIdx];
    int total = n * CG;
    for (int w = blockIdx.x * blockDim.x + threadIdx.x; w < total;
         w += gridDim.x * blockDim.x) {
        int v = list[w / CG];
        int cg = w % CG;
        int x0 = v % D, y0 = (v / D) % D, z0 = v / (D * D);
        float4 acc = make_float4(0.f, 0.f, 0.f, 0.f);
        for (int dz = -1; dz <= 1; dz++) {
            int zz = z0 + dz;
            if ((unsigned)zz >= (unsigned)D) continue;
            for (int dy = -1; dy <= 1; dy++) {
                int yy = y0 + dy;
                if ((unsigned)yy >= (unsigned)D) continue;
                for (int dx = -1; dx <= 1; dx++) {
                    int xx = x0 + dx;
                    if ((unsigned)xx >= (unsigned)D) continue;
                    int t = ((dz + 1) * 3 + (dy + 1)) * 3 + (dx + 1);
                    int noff = (zz * D + yy) * D + xx;
                    const float* ip = inA + noff;
                    const float* wp = wt + t * COPAD + cg * 4;
                    #pragma unroll
                    for (int ci = 0; ci < CINA; ci++) {
                        float iv = __ldg(ip); ip += vol;
                        float4 wv = *reinterpret_cast<const float4*>(wp);
                        wp += 27 * COPAD;
                        acc.x += iv * wv.x; acc.y += iv * wv.y;
                        acc.z += iv * wv.z; acc.w += iv * wv.w;
                    }
                    if (CINB > 0) {
                        const float* ip2 = inB + noff;
                        #pragma unroll
                        for (int ci = 0; ci < CINB; ci++) {
                            float iv = __ldg(ip2); ip2 += vol;
                            float4 wv = *reinterpret_cast<const float4*>(wp);
                            wp += 27 * COPAD;
                            acc.x += iv * wv.x; acc.y += iv * wv.y;
                            acc.z += iv * wv.z; acc.w += iv * wv.w;
                        }
                    }
                }
            }
        }
        if (RELU) {
            acc.x = fmaxf(acc.x, 0.f); acc.y = fmaxf(acc.y, 0.f);
            acc.z = fmaxf(acc.z, 0.f); acc.w = fmaxf(acc.w, 0.f);
        }
        int co = cg * 4;
        out[(co + 0) * vol + v] = acc.x;
        if (co + 1 < COUT) out[(co + 1) * vol + v] = acc.y;
        if (co + 2 < COUT) out[(co + 2) * vol + v] = acc.z;
        if (co + 3 < COUT) out[(co + 3) * vol + v] = acc.w;
    }
}

// strided k=2 s=2 conv: coarse output voxel gathers its 8 fine children
template <int CIN, int COUT, int COPAD>
__global__ __launch_bounds__(256)
void down2_kernel(const float* __restrict__ in, const float* __restrict__ wt,
                  float* __restrict__ out, const int* __restrict__ list,
                  const int* __restrict__ cnt, int cntIdx, int Dc) {
    const int Df = Dc * 2;
    const int volf = Df * Df * Df;
    const int volc = Dc * Dc * Dc;
    const int CG = COPAD / 4;
    int n = cnt[cntIdx];
    int total = n * CG;
    for (int w = blockIdx.x * blockDim.x + threadIdx.x; w < total;
         w += gridDim.x * blockDim.x) {
        int v = list[w / CG];
        int cg = w % CG;
        int x0 = v % Dc, y0 = (v / Dc) % Dc, z0 = v / (Dc * Dc);
        float4 acc = make_float4(0.f, 0.f, 0.f, 0.f);
        #pragma unroll
        for (int t = 0; t < 8; t++) {
            int tz = t >> 2, ty = (t >> 1) & 1, tx = t & 1;
            int noff = ((2 * z0 + tz) * Df + (2 * y0 + ty)) * Df + (2 * x0 + tx);
            const float* ip = in + noff;
            const float* wp = wt + t * COPAD + cg * 4;
            #pragma unroll
            for (int ci = 0; ci < CIN; ci++) {
                float iv = __ldg(ip); ip += volf;
                float4 wv = *reinterpret_cast<const float4*>(wp);
                wp += 8 * COPAD;
                acc.x += iv * wv.x; acc.y += iv * wv.y;
                acc.z += iv * wv.z; acc.w += iv * wv.w;
            }
        }
        int co = cg * 4;
        out[(co + 0) * volc + v] = acc.x;
        out[(co + 1) * volc + v] = acc.y;
        out[(co + 2) * volc + v] = acc.z;
        out[(co + 3) * volc + v] = acc.w;
    }
}

// transpose k=2 s=2 conv: fine output voxel reads its single coarse parent,
// kernel tap selected by parity (tap = 1 - parity per dim)
template <int CIN, int COUT, int COPAD>
__global__ __launch_bounds__(256)
void up2_kernel(const float* __restrict__ in, const float* __restrict__ wt,
                float* __restrict__ out, const int* __restrict__ list,
                const int* __restrict__ cnt, int cntIdx, int Df) {
    const int Dc = Df / 2;
    const int volf = Df * Df * Df;
    const int volc = Dc * Dc * Dc;
    const int CG = COPAD / 4;
    int n = cnt[cntIdx];
    int total = n * CG;
    for (int w = blockIdx.x * blockDim.x + threadIdx.x; w < total;
         w += gridDim.x * blockDim.x) {
        int v = list[w / CG];
        int cg = w % CG;
        int x0 = v % Df, y0 = (v / Df) % Df, z0 = v / (Df * Df);
        int t = ((1 - (z0 & 1)) * 2 + (1 - (y0 & 1))) * 2 + (1 - (x0 & 1));
        int coff = ((z0 >> 1) * Dc + (y0 >> 1)) * Dc + (x0 >> 1);
        float4 acc = make_float4(0.f, 0.f, 0.f, 0.f);
        const float* ip = in + coff;
        const float* wp = wt + t * COPAD + cg * 4;
        #pragma unroll
        for (int ci = 0; ci < CIN; ci++) {
            float iv = __ldg(ip); ip += volc;
            float4 wv = *reinterpret_cast<const float4*>(wp);
            wp += 8 * COPAD;
            acc.x += iv * wv.x; acc.y += iv * wv.y;
            acc.z += iv * wv.z; acc.w += iv * wv.w;
        }
        int co = cg * 4;
        out[(co + 0) * volf + v] = acc.x;
        out[(co + 1) * volf + v] = acc.y;
        out[(co + 2) * volf + v] = acc.z;
        out[(co + 3) * volf + v] = acc.w;
    }
}

// ---------------------------------------------------------------------------
// launch
// ---------------------------------------------------------------------------

extern "C" void kernel_launch(void* const* d_in, const int* in_sizes, int n_in,
                              void* d_out, int out_size) {
    (void)in_sizes; (void)n_in;
    const float* x    = (const float*)d_in[0];
    const float* occ  = (const float*)d_in[1];
    const float* w_in   = (const float*)d_in[2];
    const float* w_e0d  = (const float*)d_in[3];
    const float* w_e0a  = (const float*)d_in[4];
    const float* w_e0b  = (const float*)d_in[5];
    const float* w_e1d  = (const float*)d_in[6];
    const float* w_e1a  = (const float*)d_in[7];
    const float* w_e1b  = (const float*)d_in[8];
    const float* w_d0u  = (const float*)d_in[9];
    const float* w_d0a  = (const float*)d_in[10];
    const float* w_d0b  = (const float*)d_in[11];
    const float* w_d1u  = (const float*)d_in[12];
    const float* w_d1a  = (const float*)d_in[13];
    const float* w_d1b  = (const float*)d_in[14];
    const float* w_oa   = (const float*)d_in[15];
    const float* w_ob   = (const float*)d_in[16];
    float* out = (float*)d_out;

    float* SB = nullptr;
    int *L0 = nullptr, *L1 = nullptr, *L2 = nullptr, *CNT = nullptr;
    cudaGetSymbolAddress((void**)&SB,  g_scratch);
    cudaGetSymbolAddress((void**)&L0,  g_list0);
    cudaGetSymbolAddress((void**)&L1,  g_list1);
    cudaGetSymbolAddress((void**)&L2,  g_list2);
    cudaGetSymbolAddress((void**)&CNT, g_cnt);

    const int NT = 256;
    const int NB = 2048;           // grid-stride heavy kernels

    // 1) zero feature arena + output + counters
    zero_all_kernel<<<NB, NT>>>(out, out_size);

    // 2) masked input, coarse masks
    mask_mul_kernel<<<(V0 + NT - 1) / NT, NT>>>(x, occ, SB + OFF_XM, V0);
    maxpool_mask_kernel<<<(V1 + NT - 1) / NT, NT>>>(occ, SB + OFF_M1, D1);
    maxpool_mask_kernel<<<(V2 + NT - 1) / NT, NT>>>(SB + OFF_M1, SB + OFF_M2, D2);

    // 3) compact occupancy lists
    build_list_kernel<<<(V0 + NT - 1) / NT, NT>>>(occ,          V0, L0, CNT + 0);
    build_list_kernel<<<(V1 + NT - 1) / NT, NT>>>(SB + OFF_M1,  V1, L1, CNT + 1);
    build_list_kernel<<<(V2 + NT - 1) / NT, NT>>>(SB + OFF_M2,  V2, L2, CNT + 2);

    // 4) weight transposes  (layout: [ci*K3+t][Copad])
    auto TW = [&](const float* w, int off, int Cout, int Cin, int K3, int Copad) {
        int total = Cin * K3 * Copad;
        transpose_w_kernel<<<(total + NT - 1) / NT, NT>>>(w, SB + off, Cout, Cin, K3, Copad);
    };
    TW(w_in,  WO_IN,  16, 1,  27, 16);
    TW(w_e0d, WO_E0D, 32, 16, 8,  32);
    TW(w_e0a, WO_E0A, 32, 32, 27, 32);
    TW(w_e0b, WO_E0B, 32, 32, 27, 32);
    TW(w_e1d, WO_E1D, 64, 32, 8,  64);
    TW(w_e1a, WO_E1A, 64, 64, 27, 64);
    TW(w_e1b, WO_E1B, 64, 64, 27, 64);
    TW(w_d0u, WO_D0U, 32, 64, 8,  32);
    TW(w_d0a, WO_D0A, 64, 64, 27, 64);
    TW(w_d0b, WO_D0B, 32, 64, 27, 32);
    TW(w_d1u, WO_D1U, 16, 32, 8,  16);
    TW(w_d1a, WO_D1A, 32, 32, 27, 32);
    TW(w_d1b, WO_D1B, 16, 32, 27, 16);
    TW(w_oa,  WO_OA,  16, 16, 27, 16);
    TW(w_ob,  WO_OB,  5,  16, 27, 8);

    // 5) U-Net pipeline
    // input block: conv_in 1->16 @96, masked m0
    conv3_kernel<1, 0, 16, 16, false><<<NB, NT>>>(
        SB + OFF_XM, nullptr, SB + WO_IN, SB + OFF_SKIP0, L0, CNT, 0, D0);

    // encoder level 0
    down2_kernel<16, 32, 32><<<NB, NT>>>(
        SB + OFF_SKIP0, SB + WO_E0D, SB + OFF_HA, L1, CNT, 1, D1);
    conv3_kernel<32, 0, 32, 32, true><<<NB, NT>>>(
        SB + OFF_HA, nullptr, SB + WO_E0A, SB + OFF_HB, L1, CNT, 1, D1);
    conv3_kernel<32, 0, 32, 32, false><<<NB, NT>>>(
        SB + OFF_HB, nullptr, SB + WO_E0B, SB + OFF_S1, L1, CNT, 1, D1);

    // encoder level 1
    down2_kernel<32, 64, 64><<<NB, NT>>>(
        SB + OFF_S1, SB + WO_E1D, SB + OFF_CA, L2, CNT, 2, D2);
    conv3_kernel<64, 0, 64, 64, true><<<NB, NT>>>(
        SB + OFF_CA, nullptr, SB + WO_E1A, SB + OFF_CB, L2, CNT, 2, D2);
    conv3_kernel<64, 0, 64, 64, false><<<NB, NT>>>(
        SB + OFF_CB, nullptr, SB + WO_E1B, SB + OFF_CA, L2, CNT, 2, D2);

    // decoder stage 0 (to level 1)
    up2_kernel<64, 32, 32><<<NB, NT>>>(
        SB + OFF_CA, SB + WO_D0U, SB + OFF_HA, L1, CNT, 1, D1);
    conv3_kernel<32, 32, 64, 64, true><<<NB, NT>>>(
        SB + OFF_HA, SB + OFF_S1, SB + WO_D0A, SB + OFF_H64, L1, CNT, 1, D1);
    conv3_kernel<64, 0, 32, 32, false><<<NB, NT>>>(
        SB + OFF_H64, nullptr, SB + WO_D0B, SB + OFF_HB, L1, CNT, 1, D1);

    // decoder stage 1 (to level 0)
    up2_kernel<32, 16, 16><<<NB, NT>>>(
        SB + OFF_HB, SB + WO_D1U, SB + OFF_UP1, L0, CNT, 0, D0);
    conv3_kernel<16, 16, 32, 32, true><<<NB, NT>>>(
        SB + OFF_UP1, SB + OFF_SKIP0, SB + WO_D1A, SB + OFF_T32, L0, CNT, 0, D0);
    conv3_kernel<32, 0, 16, 16, false><<<NB, NT>>>(
        SB + OFF_T32, nullptr, SB + WO_D1B, SB + OFF_UP1, L0, CNT, 0, D0);

    // output block
    conv3_kernel<16, 0, 16, 16, true><<<NB, NT>>>(
        SB + OFF_UP1, nullptr, SB + WO_OA, SB + OFF_SKIP0, L0, CNT, 0, D0);
    conv3_kernel<16, 0, 5, 8, false><<<NB, NT>>>(
        SB + OFF_SKIP0, nullptr, SB + WO_OB, out, L0, CNT, 0, D0);
}